// round 16
// baseline (speedup 1.0000x reference)
#include <cuda_runtime.h>
#include <cuda_bf16.h>
#include <cstdint>

#define HID    2048
#define NEXP   64
#define TOPK   8
#define NTOK   16384
#define CTOK   128
#define KC     64
#define NCHUNK 32
#define THREADS 256
#define RS_H   0.022097086912079612f
#define EPSV   1e-6f
#define THETA  1e-5f
#define XSTR   72            // xh/xl smem row stride (bf16 units)
#define LSS    66            // logits smem row stride (floats)

// W packed for HMMA B-fragments: [ch][kg][e][tig] -> 4 bf16 {2t,2t+1,2t+8,2t+9}
__device__ __nv_bfloat16 g_wph[NCHUNK * 4 * NEXP * 4 * 4];
__device__ __nv_bfloat16 g_wpl[NCHUNK * 4 * NEXP * 4 * 4];
__device__ float         g_wf[NEXP * HID];
__device__ int           g_flaglist[NTOK];
__device__ int           g_flagctr, g_consume;

#define CP16(dst, src) \
    asm volatile("cp.async.ca.shared.global [%0], [%1], 16;" :: "r"(dst), "l"(src))
#define CP_COMMIT() asm volatile("cp.async.commit_group;")
#define CP_WAIT0()  asm volatile("cp.async.wait_group 0;" ::: "memory")
#define CP_WAIT1()  asm volatile("cp.async.wait_group 1;" ::: "memory")

#define MMA16816(c, a, b0, b1) \
    asm volatile("mma.sync.aligned.m16n8k16.row.col.f32.bf16.bf16.f32 " \
        "{%0,%1,%2,%3}, {%4,%5,%6,%7}, {%8,%9}, {%0,%1,%2,%3};" \
        : "+f"((c)[0]), "+f"((c)[1]), "+f"((c)[2]), "+f"((c)[3]) \
        : "r"((a)[0]), "r"((a)[1]), "r"((a)[2]), "r"((a)[3]), "r"(b0), "r"(b1))

#define O_PES  0
#define O_SSQ  256
#define O_HIST 768
#define O_LS   1024
#define O_XH   34816
#define O_XL   53248
#define O_B    71680
#define SMEM_BYTES 104448

// ---- prep ----
__global__ void prep_kernel(const float* __restrict__ pw,
                            const float* __restrict__ scale,
                            float* __restrict__ out) {
    int o = blockIdx.x * blockDim.x + threadIdx.x;
    int j   = o & 3;
    int u   = o >> 2;
    int tig = u & 3;
    int e   = (u >> 2) & 63;
    int kg  = (u >> 8) & 3;
    int ch  = u >> 10;
    int kk  = (j < 2) ? (2 * tig + j) : (2 * tig + 8 + (j - 2));
    int k   = ch * KC + kg * 16 + kk;
    float fd = pw[e * HID + k] * scale[k] * RS_H;
    g_wf[e * HID + k] = fd;
    __nv_bfloat16 h = __float2bfloat16_rn(fd);
    g_wph[o] = h;
    g_wpl[o] = __float2bfloat16_rn(fd - __bfloat162float(h));
    if (o == 0) { g_flagctr = 0; g_consume = 0; }
    if (o < NEXP) out[2 * NTOK * TOPK + o] = 0.0f;
}

// ---- phase 1: 4-term split-bf16 HMMA GEMM + certified top-8 ----
__global__ __launch_bounds__(THREADS, 1)
void router_phase1(const float* __restrict__ hs,
                   const float* __restrict__ pes,
                   float* __restrict__ out) {
    extern __shared__ char smem[];
    const uint32_t sb = (uint32_t)__cvta_generic_to_shared(smem);
    const int tid = threadIdx.x, wid = tid >> 5, lane = tid & 31;
    const int tok0 = blockIdx.x * CTOK;
    float* pes_s  = (float*)(smem + O_PES);
    float* ssq_s  = (float*)(smem + O_SSQ);
    int*   hist_s = (int*)(smem + O_HIST);
    float* ls     = (float*)(smem + O_LS);
    if (tid < NEXP) { pes_s[tid] = pes[tid]; hist_s[tid] = 0; }

    const int g16 = tid >> 4, c4 = tid & 15;
    const int gid = lane >> 2, tig = lane & 3;
    const int mw = wid >> 1;
    const int nw = wid & 1;

    int aoffb[2], boffb[4];
    #pragma unroll
    for (int mt = 0; mt < 2; mt++)
        aoffb[mt] = ((mw * 32 + 16 * mt + gid) * XSTR + 2 * tig) * 2;
    #pragma unroll
    for (int nt = 0; nt < 4; nt++)
        boffb[nt] = ((nw * 32 + 8 * nt + gid) * 4 + tig) * 8;

    auto copyB = [&](int ch, int b) {
        const char* sh = (const char*)g_wph + (size_t)ch * 8192;
        const char* sl = (const char*)g_wpl + (size_t)ch * 8192;
        uint32_t dh = sb + O_B + b * 16384;
        uint32_t dl = dh + 8192;
        #pragma unroll
        for (int j = 0; j < 2; j++) {
            int u = tid + THREADS * j;
            CP16(dh + u * 16, sh + u * 16);
            CP16(dl + u * 16, sl + u * 16);
        }
        CP_COMMIT();
    };

    float4 xr[8];
    #pragma unroll
    for (int j = 0; j < 8; j++)
        xr[j] = *(const float4*)(hs + (size_t)(tok0 + g16 + 16 * j) * HID + c4 * 4);
    copyB(0, 0);

    float acc[2][4][4];
    #pragma unroll
    for (int mt = 0; mt < 2; mt++)
        #pragma unroll
        for (int nt = 0; nt < 4; nt++)
            #pragma unroll
            for (int q = 0; q < 4; q++) acc[mt][nt][q] = 0.f;
    float ssqa[8];
    #pragma unroll
    for (int j = 0; j < 8; j++) ssqa[j] = 0.f;

    for (int ch = 0; ch < NCHUNK; ch++) {
        const int b = ch & 1;
        #pragma unroll
        for (int j = 0; j < 8; j++) {
            int row = g16 + 16 * j;
            float4 x = xr[j];
            ssqa[j] += x.x * x.x + x.y * x.y + x.z * x.z + x.w * x.w;
            __nv_bfloat16 h0 = __float2bfloat16_rn(x.x), h1 = __float2bfloat16_rn(x.y);
            __nv_bfloat16 h2 = __float2bfloat16_rn(x.z), h3 = __float2bfloat16_rn(x.w);
            __nv_bfloat162 hp0 = {h0, h1}, hp1 = {h2, h3};
            __nv_bfloat162 lp0 = {__float2bfloat16_rn(x.x - __bfloat162float(h0)),
                                  __float2bfloat16_rn(x.y - __bfloat162float(h1))};
            __nv_bfloat162 lp1 = {__float2bfloat16_rn(x.z - __bfloat162float(h2)),
                                  __float2bfloat16_rn(x.w - __bfloat162float(h3))};
            uint2 hv = {*(uint32_t*)&hp0, *(uint32_t*)&hp1};
            uint2 lv = {*(uint32_t*)&lp0, *(uint32_t*)&lp1};
            int off = (row * XSTR + c4 * 4) * 2;
            *(uint2*)(smem + O_XH + off) = hv;
            *(uint2*)(smem + O_XL + off) = lv;
        }
        if (ch + 1 < NCHUNK) {
            #pragma unroll
            for (int j = 0; j < 8; j++)
                xr[j] = *(const float4*)(hs + (size_t)(tok0 + g16 + 16 * j) * HID
                                         + (ch + 1) * KC + c4 * 4);
            copyB(ch + 1, b ^ 1);
            CP_WAIT1();
        } else {
            CP_WAIT0();
        }
        __syncthreads();

        const char* bhp = smem + O_B + b * 16384;
        const char* blp = bhp + 8192;
        #pragma unroll
        for (int s = 0; s < 4; s++) {
            uint32_t ah[2][4], al[2][4];
            #pragma unroll
            for (int mt = 0; mt < 2; mt++) {
                int ab = aoffb[mt] + s * 32;
                ah[mt][0] = *(const uint32_t*)(smem + O_XH + ab);
                ah[mt][1] = *(const uint32_t*)(smem + O_XH + ab + 1152);
                ah[mt][2] = *(const uint32_t*)(smem + O_XH + ab + 16);
                ah[mt][3] = *(const uint32_t*)(smem + O_XH + ab + 1168);
                al[mt][0] = *(const uint32_t*)(smem + O_XL + ab);
                al[mt][1] = *(const uint32_t*)(smem + O_XL + ab + 1152);
                al[mt][2] = *(const uint32_t*)(smem + O_XL + ab + 16);
                al[mt][3] = *(const uint32_t*)(smem + O_XL + ab + 1168);
            }
            uint2 bh[4], bl[4];
            #pragma unroll
            for (int nt = 0; nt < 4; nt++) {
                int bb = boffb[nt] + s * 2048;
                bh[nt] = *(const uint2*)(bhp + bb);
                bl[nt] = *(const uint2*)(blp + bb);
            }
            #pragma unroll
            for (int mt = 0; mt < 2; mt++)
                #pragma unroll
                for (int nt = 0; nt < 4; nt++) {
                    MMA16816(acc[mt][nt], ah[mt], bh[nt].x, bh[nt].y);
                    MMA16816(acc[mt][nt], ah[mt], bl[nt].x, bl[nt].y);
                    MMA16816(acc[mt][nt], al[mt], bh[nt].x, bh[nt].y);
                    MMA16816(acc[mt][nt], al[mt], bl[nt].x, bl[nt].y);
                }
        }
        __syncthreads();
    }

    #pragma unroll
    for (int j = 0; j < 8; j++) {
        float v = ssqa[j];
        v += __shfl_xor_sync(0xffffffffu, v, 1);
        v += __shfl_xor_sync(0xffffffffu, v, 2);
        v += __shfl_xor_sync(0xffffffffu, v, 4);
        v += __shfl_xor_sync(0xffffffffu, v, 8);
        if (c4 == 0) ssq_s[16 * j + g16] = v;
    }

    #pragma unroll
    for (int mt = 0; mt < 2; mt++)
        #pragma unroll
        for (int nt = 0; nt < 4; nt++) {
            int row = mw * 32 + 16 * mt + gid;
            int col = nw * 32 + 8 * nt + 2 * tig;
            ls[row * LSS + col]           = acc[mt][nt][0];
            ls[row * LSS + col + 1]       = acc[mt][nt][1];
            ls[(row + 8) * LSS + col]     = acc[mt][nt][2];
            ls[(row + 8) * LSS + col + 1] = acc[mt][nt][3];
        }
    __syncthreads();

    for (int t = wid * 16; t < wid * 16 + 16; t++) {
        float f = rsqrtf(ssq_s[t] * (1.0f / HID) + EPSV);
        float v0 = ls[t * LSS + lane] * f;
        float v1 = ls[t * LSS + lane + 32] * f;
        float myv = 0.f, top0 = 0.f, prev = 0.f;
        int myi = 0, flag = 0;
        #pragma unroll
        for (int r = 0; r < 9; r++) {
            float bv = v0; int bi = lane;
            if (v1 > bv) { bv = v1; bi = lane + 32; }
            #pragma unroll
            for (int s = 16; s > 0; s >>= 1) {
                float ov = __shfl_xor_sync(0xffffffffu, bv, s);
                int   oi = __shfl_xor_sync(0xffffffffu, bi, s);
                if (ov > bv || (ov == bv && oi < bi)) { bv = ov; bi = oi; }
            }
            if (r == 0) top0 = bv;
            else flag |= (prev - bv < THETA);
            prev = bv;
            if (lane == r) { myv = bv; myi = bi; }
            if (bi == lane)           v0 = -3.4e38f;
            else if (bi == lane + 32) v1 = -3.4e38f;
        }
        int gt = tok0 + t;
        if (flag) {
            if (lane == 0) g_flaglist[atomicAdd(&g_flagctr, 1)] = gt;
        } else {
            float q = (lane < TOPK) ? expf(myv - top0) : 0.f;
            float wsum = q;
            #pragma unroll
            for (int s = 16; s > 0; s >>= 1)
                wsum += __shfl_xor_sync(0xffffffffu, wsum, s);
            if (lane < TOPK) {
                out[(size_t)gt * TOPK + lane] = q / wsum * pes_s[myi];
                out[(size_t)NTOK * TOPK + (size_t)gt * TOPK + lane] = (float)myi;
                atomicAdd(&hist_s[myi], 1);
            }
        }
    }
    __syncthreads();
    if (tid < NEXP)
        atomicAdd(&out[2 * NTOK * TOPK + tid], (float)hist_s[tid]);
}

// ---- phase 2: exact fp32 rescore, contraction PINNED to the proven tree ----
__global__ __launch_bounds__(256)
void router_exact(const float* __restrict__ hs,
                  const float* __restrict__ pes,
                  float* __restrict__ out) {
    const int lane = threadIdx.x & 31;
    const int n = *(volatile int*)&g_flagctr;
    for (;;) {
        int widx = 0;
        if (lane == 0) widx = atomicAdd(&g_consume, 1);
        widx = __shfl_sync(0xffffffffu, widx, 0);
        if (widx >= n) return;
        const int gt = g_flaglist[widx];
        const float* x = hs + (size_t)gt * HID;

        float ss = 0.f;
        for (int k = lane * 4; k < HID; k += 128) {
            float4 v = *(const float4*)(x + k);
            ss += v.x * v.x + v.y * v.y + v.z * v.z + v.w * v.w;
        }
        #pragma unroll
        for (int s = 16; s > 0; s >>= 1) ss += __shfl_xor_sync(0xffffffffu, ss, s);
        float f = rsqrtf(ss * (1.0f / HID) + EPSV);

        // logits: T = mul,fma,fma,fma ; acc = add(acc, T) per k4, k ascending —
        // op-for-op the contraction that passed rounds 2/8/9/11 (rel_err 9.36e-8)
        float a0 = 0.f, a1 = 0.f;
        const float* w0 = g_wf + (size_t)lane * HID;
        const float* w1 = g_wf + (size_t)(lane + 32) * HID;
        for (int k = 0; k < HID; k += 4) {
            float4 xv = *(const float4*)(x + k);
            float4 wa = *(const float4*)(w0 + k);
            float4 wb = *(const float4*)(w1 + k);
            float T0 = __fmul_rn(xv.x, wa.x);
            T0 = __fmaf_rn(xv.y, wa.y, T0);
            T0 = __fmaf_rn(xv.z, wa.z, T0);
            T0 = __fmaf_rn(xv.w, wa.w, T0);
            a0 = __fadd_rn(a0, T0);
            float T1 = __fmul_rn(xv.x, wb.x);
            T1 = __fmaf_rn(xv.y, wb.y, T1);
            T1 = __fmaf_rn(xv.z, wb.z, T1);
            T1 = __fmaf_rn(xv.w, wb.w, T1);
            a1 = __fadd_rn(a1, T1);
        }
        float v0 = __fmul_rn(a0, f), v1 = __fmul_rn(a1, f);
        float myv = 0.f, top0 = 0.f;
        int myi = 0;
        #pragma unroll
        for (int r = 0; r < TOPK; r++) {
            float bv = v0; int bi = lane;
            if (v1 > bv) { bv = v1; bi = lane + 32; }
            #pragma unroll
            for (int s = 16; s > 0; s >>= 1) {
                float ov = __shfl_xor_sync(0xffffffffu, bv, s);
                int   oi = __shfl_xor_sync(0xffffffffu, bi, s);
                if (ov > bv || (ov == bv && oi < bi)) { bv = ov; bi = oi; }
            }
            if (r == 0) top0 = bv;
            if (lane == r) { myv = bv; myi = bi; }
            if (bi == lane)           v0 = -3.4e38f;
            else if (bi == lane + 32) v1 = -3.4e38f;
        }
        float q = (lane < TOPK) ? expf(myv - top0) : 0.f;
        float wsum = q;
        #pragma unroll
        for (int s = 16; s > 0; s >>= 1)
            wsum += __shfl_xor_sync(0xffffffffu, wsum, s);
        if (lane < TOPK) {
            out[(size_t)gt * TOPK + lane] = q / wsum * pes[myi];
            out[(size_t)NTOK * TOPK + (size_t)gt * TOPK + lane] = (float)myi;
            atomicAdd(&out[2 * NTOK * TOPK + myi], 1.0f);
        }
    }
}

extern "C" void kernel_launch(void* const* d_in, const int* in_sizes, int n_in,
                              void* d_out, int out_size) {
    const float* hs    = (const float*)d_in[0];
    const float* scale = (const float*)d_in[1];
    const float* pw    = (const float*)d_in[2];
    const float* pes   = (const float*)d_in[3];
    float* out = (float*)d_out;

    cudaFuncSetAttribute(router_phase1,
                         cudaFuncAttributeMaxDynamicSharedMemorySize, SMEM_BYTES);
    prep_kernel<<<(NEXP * HID) / 256, 256>>>(pw, scale, out);
    router_phase1<<<NTOK / CTOK, THREADS, SMEM_BYTES>>>(hs, pes, out);
    router_exact<<<64, 256>>>(hs, pes, out);
}

// round 17
// speedup vs baseline: 1.1271x; 1.1271x over previous
#include <cuda_runtime.h>
#include <cuda_bf16.h>
#include <cstdint>

#define HID    2048
#define NEXP   64
#define TOPK   8
#define NTOK   16384
#define CTOK   64
#define KC     64
#define NCHUNK 32
#define THREADS 256
#define RS_H   0.022097086912079612f
#define EPSV   1e-6f
#define THETA  1e-5f
#define XSTR   72            // xh/xl smem row stride (bf16 units)
#define LSS    66            // logits smem row stride (floats)

// W packed for HMMA B-fragments: [ch][kg][e][tig] -> 4 bf16 {2t,2t+1,2t+8,2t+9}
__device__ __nv_bfloat16 g_wph[NCHUNK * 4 * NEXP * 4 * 4];
__device__ __nv_bfloat16 g_wpl[NCHUNK * 4 * NEXP * 4 * 4];
__device__ float         g_wf[NEXP * HID];
__device__ int           g_flaglist[NTOK];
__device__ int           g_flagctr, g_consume;

#define CP16(dst, src) \
    asm volatile("cp.async.ca.shared.global [%0], [%1], 16;" :: "r"(dst), "l"(src))
#define CP_COMMIT() asm volatile("cp.async.commit_group;")
#define CP_WAIT0()  asm volatile("cp.async.wait_group 0;" ::: "memory")
#define CP_WAIT1()  asm volatile("cp.async.wait_group 1;" ::: "memory")

#define MMA16816(c, a, b0, b1) \
    asm volatile("mma.sync.aligned.m16n8k16.row.col.f32.bf16.bf16.f32 " \
        "{%0,%1,%2,%3}, {%4,%5,%6,%7}, {%8,%9}, {%0,%1,%2,%3};" \
        : "+f"((c)[0]), "+f"((c)[1]), "+f"((c)[2]), "+f"((c)[3]) \
        : "r"((a)[0]), "r"((a)[1]), "r"((a)[2]), "r"((a)[3]), "r"(b0), "r"(b1))

// smem byte offsets (CTOK=64)
#define O_PES  0
#define O_SSQ  256
#define O_HIST 512
#define O_XH   1024                      // 64 x 72 bf16 = 9216
#define O_XL   10240                     // 9216
#define O_B    19456                     // BH0|BL0|BH1|BL1, 8192 each = 32768
#define O_LS   1024                      // ALIAS over XH/XL (dead after GEMM)
#define SMEM_BYTES 52224

// ---- prep ----
__global__ void prep_kernel(const float* __restrict__ pw,
                            const float* __restrict__ scale,
                            float* __restrict__ out) {
    int o = blockIdx.x * blockDim.x + threadIdx.x;
    int j   = o & 3;
    int u   = o >> 2;
    int tig = u & 3;
    int e   = (u >> 2) & 63;
    int kg  = (u >> 8) & 3;
    int ch  = u >> 10;
    int kk  = (j < 2) ? (2 * tig + j) : (2 * tig + 8 + (j - 2));
    int k   = ch * KC + kg * 16 + kk;
    float fd = pw[e * HID + k] * scale[k] * RS_H;
    g_wf[e * HID + k] = fd;
    __nv_bfloat16 h = __float2bfloat16_rn(fd);
    g_wph[o] = h;
    g_wpl[o] = __float2bfloat16_rn(fd - __bfloat162float(h));
    if (o == 0) { g_flagctr = 0; g_consume = 0; }
    if (o < NEXP) out[2 * NTOK * TOPK + o] = 0.0f;
}

// ---- phase 1: 3-term split-bf16 HMMA GEMM + certified top-8 ----
__global__ __launch_bounds__(THREADS, 2)
void router_phase1(const float* __restrict__ hs,
                   const float* __restrict__ pes,
                   float* __restrict__ out) {
    extern __shared__ char smem[];
    const uint32_t sb = (uint32_t)__cvta_generic_to_shared(smem);
    const int tid = threadIdx.x, wid = tid >> 5, lane = tid & 31;
    const int tok0 = blockIdx.x * CTOK;
    float* pes_s  = (float*)(smem + O_PES);
    float* ssq_s  = (float*)(smem + O_SSQ);
    int*   hist_s = (int*)(smem + O_HIST);
    float* ls     = (float*)(smem + O_LS);
    if (tid < NEXP) { pes_s[tid] = pes[tid]; hist_s[tid] = 0; }

    const int g16 = tid >> 4, c4 = tid & 15;
    const int gid = lane >> 2, tig = lane & 3;
    const int mw = wid >> 1;          // token group: rows mw*16 .. +15
    const int nw = wid & 1;           // expert group: nw*32 .. +31

    const int aoffb = ((mw * 16 + gid) * XSTR + 2 * tig) * 2;
    int boffb[4];
    #pragma unroll
    for (int nt = 0; nt < 4; nt++)
        boffb[nt] = ((nw * 32 + 8 * nt + gid) * 4 + tig) * 8;

    auto copyB = [&](int ch, int b) {
        const char* sh = (const char*)g_wph + (size_t)ch * 8192;
        const char* sl = (const char*)g_wpl + (size_t)ch * 8192;
        uint32_t dh = sb + O_B + b * 16384;
        uint32_t dl = dh + 8192;
        #pragma unroll
        for (int j = 0; j < 2; j++) {
            int u = tid + THREADS * j;
            CP16(dh + u * 16, sh + u * 16);
            CP16(dl + u * 16, sl + u * 16);
        }
        CP_COMMIT();
    };

    float4 xr[4];
    #pragma unroll
    for (int j = 0; j < 4; j++)
        xr[j] = *(const float4*)(hs + (size_t)(tok0 + g16 + 16 * j) * HID + c4 * 4);
    copyB(0, 0);

    float acc[4][4];
    #pragma unroll
    for (int nt = 0; nt < 4; nt++)
        #pragma unroll
        for (int q = 0; q < 4; q++) acc[nt][q] = 0.f;
    float ssqa[4] = {0.f, 0.f, 0.f, 0.f};

    for (int ch = 0; ch < NCHUNK; ch++) {
        const int b = ch & 1;
        #pragma unroll
        for (int j = 0; j < 4; j++) {
            int row = g16 + 16 * j;
            float4 x = xr[j];
            ssqa[j] += x.x * x.x + x.y * x.y + x.z * x.z + x.w * x.w;
            __nv_bfloat16 h0 = __float2bfloat16_rn(x.x), h1 = __float2bfloat16_rn(x.y);
            __nv_bfloat16 h2 = __float2bfloat16_rn(x.z), h3 = __float2bfloat16_rn(x.w);
            __nv_bfloat162 hp0 = {h0, h1}, hp1 = {h2, h3};
            __nv_bfloat162 lp0 = {__float2bfloat16_rn(x.x - __bfloat162float(h0)),
                                  __float2bfloat16_rn(x.y - __bfloat162float(h1))};
            __nv_bfloat162 lp1 = {__float2bfloat16_rn(x.z - __bfloat162float(h2)),
                                  __float2bfloat16_rn(x.w - __bfloat162float(h3))};
            uint2 hv = {*(uint32_t*)&hp0, *(uint32_t*)&hp1};
            uint2 lv = {*(uint32_t*)&lp0, *(uint32_t*)&lp1};
            int off = (row * XSTR + c4 * 4) * 2;
            *(uint2*)(smem + O_XH + off) = hv;
            *(uint2*)(smem + O_XL + off) = lv;
        }
        if (ch + 1 < NCHUNK) {
            #pragma unroll
            for (int j = 0; j < 4; j++)
                xr[j] = *(const float4*)(hs + (size_t)(tok0 + g16 + 16 * j) * HID
                                         + (ch + 1) * KC + c4 * 4);
            copyB(ch + 1, b ^ 1);
            CP_WAIT1();
        } else {
            CP_WAIT0();
        }
        __syncthreads();

        const char* bhp = smem + O_B + b * 16384;
        const char* blp = bhp + 8192;
        #pragma unroll
        for (int s = 0; s < 4; s++) {
            uint32_t ah[4], al[4];
            int ab = aoffb + s * 32;
            ah[0] = *(const uint32_t*)(smem + O_XH + ab);
            ah[1] = *(const uint32_t*)(smem + O_XH + ab + 1152);
            ah[2] = *(const uint32_t*)(smem + O_XH + ab + 16);
            ah[3] = *(const uint32_t*)(smem + O_XH + ab + 1168);
            al[0] = *(const uint32_t*)(smem + O_XL + ab);
            al[1] = *(const uint32_t*)(smem + O_XL + ab + 1152);
            al[2] = *(const uint32_t*)(smem + O_XL + ab + 16);
            al[3] = *(const uint32_t*)(smem + O_XL + ab + 1168);
            uint2 bh[4], bl[4];
            #pragma unroll
            for (int nt = 0; nt < 4; nt++) {
                int bb = boffb[nt] + s * 2048;
                bh[nt] = *(const uint2*)(bhp + bb);
                bl[nt] = *(const uint2*)(blp + bb);
            }
            #pragma unroll
            for (int nt = 0; nt < 4; nt++) {
                MMA16816(acc[nt], ah, bh[nt].x, bh[nt].y);
                MMA16816(acc[nt], ah, bl[nt].x, bl[nt].y);
                MMA16816(acc[nt], al, bh[nt].x, bh[nt].y);
            }
        }
        __syncthreads();
    }

    #pragma unroll
    for (int j = 0; j < 4; j++) {
        float v = ssqa[j];
        v += __shfl_xor_sync(0xffffffffu, v, 1);
        v += __shfl_xor_sync(0xffffffffu, v, 2);
        v += __shfl_xor_sync(0xffffffffu, v, 4);
        v += __shfl_xor_sync(0xffffffffu, v, 8);
        if (c4 == 0) ssq_s[16 * j + g16] = v;
    }
    __syncthreads();          // XH/XL/B dead; ls aliases them

    #pragma unroll
    for (int nt = 0; nt < 4; nt++) {
        int row = mw * 16 + gid;
        int col = nw * 32 + 8 * nt + 2 * tig;
        ls[row * LSS + col]           = acc[nt][0];
        ls[row * LSS + col + 1]       = acc[nt][1];
        ls[(row + 8) * LSS + col]     = acc[nt][2];
        ls[(row + 8) * LSS + col + 1] = acc[nt][3];
    }
    __syncthreads();

    // certified top-8: 9 selection rounds; flag if any adjacent gap < THETA
    for (int t = wid * 8; t < wid * 8 + 8; t++) {
        float f = rsqrtf(ssq_s[t] * (1.0f / HID) + EPSV);
        float v0 = ls[t * LSS + lane] * f;
        float v1 = ls[t * LSS + lane + 32] * f;
        float myv = 0.f, top0 = 0.f, prev = 0.f;
        int myi = 0, flag = 0;
        #pragma unroll
        for (int r = 0; r < 9; r++) {
            float bv = v0; int bi = lane;
            if (v1 > bv) { bv = v1; bi = lane + 32; }
            #pragma unroll
            for (int s = 16; s > 0; s >>= 1) {
                float ov = __shfl_xor_sync(0xffffffffu, bv, s);
                int   oi = __shfl_xor_sync(0xffffffffu, bi, s);
                if (ov > bv || (ov == bv && oi < bi)) { bv = ov; bi = oi; }
            }
            if (r == 0) top0 = bv;
            else flag |= (prev - bv < THETA);
            prev = bv;
            if (lane == r) { myv = bv; myi = bi; }
            if (bi == lane)           v0 = -3.4e38f;
            else if (bi == lane + 32) v1 = -3.4e38f;
        }
        int gt = tok0 + t;
        if (flag) {
            if (lane == 0) g_flaglist[atomicAdd(&g_flagctr, 1)] = gt;
        } else {
            float q = (lane < TOPK) ? expf(myv - top0) : 0.f;
            float wsum = q;
            #pragma unroll
            for (int s = 16; s > 0; s >>= 1)
                wsum += __shfl_xor_sync(0xffffffffu, wsum, s);
            if (lane < TOPK) {
                out[(size_t)gt * TOPK + lane] = q / wsum * pes_s[myi];
                out[(size_t)NTOK * TOPK + (size_t)gt * TOPK + lane] = (float)myi;
                atomicAdd(&hist_s[myi], 1);
            }
        }
    }
    __syncthreads();
    if (tid < NEXP)
        atomicAdd(&out[2 * NTOK * TOPK + tid], (float)hist_s[tid]);
}

// ---- phase 2: exact fp32 rescore, contraction PINNED to the proven tree ----
__global__ __launch_bounds__(256)
void router_exact(const float* __restrict__ hs,
                  const float* __restrict__ pes,
                  float* __restrict__ out) {
    const int lane = threadIdx.x & 31;
    const int n = *(volatile int*)&g_flagctr;
    for (;;) {
        int widx = 0;
        if (lane == 0) widx = atomicAdd(&g_consume, 1);
        widx = __shfl_sync(0xffffffffu, widx, 0);
        if (widx >= n) return;
        const int gt = g_flaglist[widx];
        const float* x = hs + (size_t)gt * HID;

        float ss = 0.f;
        for (int k = lane * 4; k < HID; k += 128) {
            float4 v = *(const float4*)(x + k);
            ss += v.x * v.x + v.y * v.y + v.z * v.z + v.w * v.w;
        }
        #pragma unroll
        for (int s = 16; s > 0; s >>= 1) ss += __shfl_xor_sync(0xffffffffu, ss, s);
        float f = rsqrtf(ss * (1.0f / HID) + EPSV);

        float a0 = 0.f, a1 = 0.f;
        const float* w0 = g_wf + (size_t)lane * HID;
        const float* w1 = g_wf + (size_t)(lane + 32) * HID;
        for (int k = 0; k < HID; k += 4) {
            float4 xv = *(const float4*)(x + k);
            float4 wa = *(const float4*)(w0 + k);
            float4 wb = *(const float4*)(w1 + k);
            float T0 = __fmul_rn(xv.x, wa.x);
            T0 = __fmaf_rn(xv.y, wa.y, T0);
            T0 = __fmaf_rn(xv.z, wa.z, T0);
            T0 = __fmaf_rn(xv.w, wa.w, T0);
            a0 = __fadd_rn(a0, T0);
            float T1 = __fmul_rn(xv.x, wb.x);
            T1 = __fmaf_rn(xv.y, wb.y, T1);
            T1 = __fmaf_rn(xv.z, wb.z, T1);
            T1 = __fmaf_rn(xv.w, wb.w, T1);
            a1 = __fadd_rn(a1, T1);
        }
        float v0 = __fmul_rn(a0, f), v1 = __fmul_rn(a1, f);
        float myv = 0.f, top0 = 0.f;
        int myi = 0;
        #pragma unroll
        for (int r = 0; r < TOPK; r++) {
            float bv = v0; int bi = lane;
            if (v1 > bv) { bv = v1; bi = lane + 32; }
            #pragma unroll
            for (int s = 16; s > 0; s >>= 1) {
                float ov = __shfl_xor_sync(0xffffffffu, bv, s);
                int   oi = __shfl_xor_sync(0xffffffffu, bi, s);
                if (ov > bv || (ov == bv && oi < bi)) { bv = ov; bi = oi; }
            }
            if (r == 0) top0 = bv;
            if (lane == r) { myv = bv; myi = bi; }
            if (bi == lane)           v0 = -3.4e38f;
            else if (bi == lane + 32) v1 = -3.4e38f;
        }
        float q = (lane < TOPK) ? expf(myv - top0) : 0.f;
        float wsum = q;
        #pragma unroll
        for (int s = 16; s > 0; s >>= 1)
            wsum += __shfl_xor_sync(0xffffffffu, wsum, s);
        if (lane < TOPK) {
            out[(size_t)gt * TOPK + lane] = q / wsum * pes[myi];
            out[(size_t)NTOK * TOPK + (size_t)gt * TOPK + lane] = (float)myi;
            atomicAdd(&out[2 * NTOK * TOPK + myi], 1.0f);
        }
    }
}

extern "C" void kernel_launch(void* const* d_in, const int* in_sizes, int n_in,
                              void* d_out, int out_size) {
    const float* hs    = (const float*)d_in[0];
    const float* scale = (const float*)d_in[1];
    const float* pw    = (const float*)d_in[2];
    const float* pes   = (const float*)d_in[3];
    float* out = (float*)d_out;

    cudaFuncSetAttribute(router_phase1,
                         cudaFuncAttributeMaxDynamicSharedMemorySize, SMEM_BYTES);
    prep_kernel<<<(NEXP * HID) / 256, 256>>>(pw, scale, out);
    router_phase1<<<NTOK / CTOK, THREADS, SMEM_BYTES>>>(hs, pes, out);
    router_exact<<<64, 256>>>(hs, pes, out);
}